// round 1
// baseline (speedup 1.0000x reference)
#include <cuda_runtime.h>

#define BATCH 36
#define TWIN 60
#define DECAY 0.3f
#define THRESH 0.5f

// ---------------- persistent state (zeroed every kernel_launch) ----------------
__device__ __align__(16) float g_c0_mem[BATCH*64*32*32];
__device__ __align__(16) float g_c0_spk[BATCH*64*32*32];
__device__ __align__(16) float g_c1_mem[BATCH*128*32*32];
__device__ __align__(16) float g_c1_spk[BATCH*128*32*32];
__device__ __align__(16) float g_p1_mem[BATCH*128*16*16];
__device__ __align__(16) float g_p1_spk[BATCH*128*16*16];
__device__ __align__(16) float g_c2_mem[BATCH*128*16*16];
__device__ __align__(16) float g_c2_spk[BATCH*128*16*16];
__device__ __align__(16) float g_p2_mem[BATCH*128*8*8];
__device__ __align__(16) float g_p2_spk[BATCH*128*8*8];
__device__ __align__(16) float g_h1_mem[BATCH*256];
__device__ __align__(16) float g_h1_spk[BATCH*256];
__device__ __align__(16) float g_h2_mem[BATCH*11];
__device__ __align__(16) float g_h2_spk[BATCH*11];
__device__ __align__(16) float g_acc[BATCH*11];

// ---------------- inter-layer activations (overwritten each step) ----------------
__device__ __align__(16) float g_act0 [BATCH*64*32*32];
__device__ __align__(16) float g_act1 [BATCH*128*32*32];
__device__ __align__(16) float g_actp1[BATCH*128*16*16];
__device__ __align__(16) float g_actc2[BATCH*128*16*16];
__device__ __align__(16) float g_actp2[BATCH*128*8*8];
__device__ __align__(16) float g_acth1[BATCH*256];

__device__ __forceinline__ float liaf_update(float u, float* memp, float* spkp) {
    float m = *memp;
    float s = *spkp;
    m = m * DECAY * (1.0f - s) + u;
    *memp = m;
    *spkp = (m > THRESH) ? 1.0f : 0.0f;
    return fmaxf(m, 0.0f);
}

// ---------------- zero state ----------------
__global__ void zero_state_kernel() {
    int i = blockIdx.x * blockDim.x + threadIdx.x;
    if (i < BATCH*64*32*32)  { g_c0_mem[i] = 0.f; g_c0_spk[i] = 0.f; }
    if (i < BATCH*128*32*32) { g_c1_mem[i] = 0.f; g_c1_spk[i] = 0.f; }
    if (i < BATCH*128*16*16) { g_p1_mem[i] = 0.f; g_p1_spk[i] = 0.f;
                               g_c2_mem[i] = 0.f; g_c2_spk[i] = 0.f; }
    if (i < BATCH*128*8*8)   { g_p2_mem[i] = 0.f; g_p2_spk[i] = 0.f; }
    if (i < BATCH*256)       { g_h1_mem[i] = 0.f; g_h1_spk[i] = 0.f; }
    if (i < BATCH*11)        { g_h2_mem[i] = 0.f; g_h2_spk[i] = 0.f; g_acc[i] = 0.f; }
}

// ---------------- conv0: binarize + 2->64 conv + LIAF ----------------
// grid (16, 36), block 256: thread = pixel(64) x ocgroup(4 of 16ch)
__global__ __launch_bounds__(256) void conv0_kernel(
    const float* __restrict__ data, const float* __restrict__ W0,
    const float* __restrict__ b0, int t)
{
    __shared__ float xs[2][10][12];
    __shared__ float ws[64][19];
    int tile = blockIdx.x, b = blockIdx.y;
    int ty0 = (tile >> 2) * 8, tx0 = (tile & 3) * 8;
    int tid = threadIdx.x;

    for (int i = tid; i < 200; i += 256) {
        int ic = i / 100, r = (i / 10) % 10, c = i % 10;
        int gy = ty0 + r - 1, gx = tx0 + c - 1;
        float v = 0.f;
        if ((unsigned)gy < 32u && (unsigned)gx < 32u) {
            float d = data[(size_t)((((b*2 + ic)*32 + gy)*32 + gx)) * TWIN + t];
            v = (d > 1.0f) ? 1.0f : 0.0f;
        }
        xs[ic][r][c] = v;
    }
    for (int i = tid; i < 1152; i += 256) {
        int oc = i / 18, r = i % 18;
        ws[oc][r] = W0[i];
    }
    __syncthreads();

    int p  = tid & 63;
    int cg = tid >> 6;
    int py = p >> 3, px = p & 7;
    int oc0 = cg * 16;

    float acc[16];
#pragma unroll
    for (int o = 0; o < 16; o++) acc[o] = 0.f;

#pragma unroll
    for (int ic = 0; ic < 2; ic++) {
        float xr[9];
#pragma unroll
        for (int r = 0; r < 3; r++)
#pragma unroll
            for (int c = 0; c < 3; c++)
                xr[r*3 + c] = xs[ic][py + r][px + c];
#pragma unroll
        for (int k = 0; k < 9; k++) {
            float x = xr[k];
#pragma unroll
            for (int o = 0; o < 16; o++)
                acc[o] = fmaf(x, ws[oc0 + o][ic*9 + k], acc[o]);
        }
    }

    int gy = ty0 + py, gx = tx0 + px;
#pragma unroll
    for (int o = 0; o < 16; o++) {
        int oc = oc0 + o;
        int idx = ((b*64 + oc)*32 + gy)*32 + gx;
        float u = acc[o] + b0[oc];
        g_act0[idx] = liaf_update(u, &g_c0_mem[idx], &g_c0_spk[idx]);
    }
}

// ---------------- generic 3x3 conv (CIN->128) + LIAF ----------------
// block 256: thread = 2x2 pixel quad (16 quads) x 8 oc (16 groups); tile 8x8.
template<int CIN, int HW>
__device__ __forceinline__ void conv_body(
    const float* __restrict__ in, const float* __restrict__ W,
    const float* __restrict__ bias, float* __restrict__ out,
    float* __restrict__ mem, float* __restrict__ spk)
{
    __shared__ float xs[8][10][12];
    __shared__ float ws[128][73];

    const int TPD = HW / 8;
    int tile = blockIdx.x, b = blockIdx.y;
    int ty0 = (tile / TPD) * 8, tx0 = (tile % TPD) * 8;
    int tid = threadIdx.x;

    int qp = tid & 15, cg = tid >> 4;
    int qy = (qp >> 2) * 2, qx = (qp & 3) * 2;
    int oc0 = cg * 8;

    float acc[2][2][8];
#pragma unroll
    for (int py = 0; py < 2; py++)
#pragma unroll
        for (int px = 0; px < 2; px++)
#pragma unroll
            for (int o = 0; o < 8; o++) acc[py][px][o] = 0.f;

    for (int ch = 0; ch < CIN/8; ch++) {
        __syncthreads();
        // input tile 8 ch x 10x10 (halo, zero-pad)
        for (int i = tid; i < 800; i += 256) {
            int icl = i / 100, r = (i / 10) % 10, c = i % 10;
            int gy = ty0 + r - 1, gx = tx0 + c - 1;
            float v = 0.f;
            if ((unsigned)gy < (unsigned)HW && (unsigned)gx < (unsigned)HW)
                v = in[((b*CIN + ch*8 + icl)*HW + gy)*HW + gx];
            xs[icl][r][c] = v;
        }
        // weights: 128 oc x (8 ic x 9) — coalesced (72 contiguous per oc)
        for (int i = tid; i < 9216; i += 256) {
            int oc = i / 72, r = i % 72;
            ws[oc][r] = W[(size_t)(oc*CIN + ch*8)*9 + r];
        }
        __syncthreads();

#pragma unroll
        for (int icl = 0; icl < 8; icl++) {
            float xr[4][4];
#pragma unroll
            for (int r = 0; r < 4; r++)
#pragma unroll
                for (int c = 0; c < 4; c++)
                    xr[r][c] = xs[icl][qy + r][qx + c];
#pragma unroll
            for (int ky = 0; ky < 3; ky++)
#pragma unroll
                for (int kx = 0; kx < 3; kx++) {
                    float w8[8];
#pragma unroll
                    for (int o = 0; o < 8; o++)
                        w8[o] = ws[oc0 + o][icl*9 + ky*3 + kx];
#pragma unroll
                    for (int py = 0; py < 2; py++)
#pragma unroll
                        for (int px = 0; px < 2; px++) {
                            float x = xr[py + ky][px + kx];
#pragma unroll
                            for (int o = 0; o < 8; o++)
                                acc[py][px][o] = fmaf(x, w8[o], acc[py][px][o]);
                        }
                }
        }
    }

#pragma unroll
    for (int py = 0; py < 2; py++)
#pragma unroll
        for (int px = 0; px < 2; px++) {
            int gy = ty0 + qy + py, gx = tx0 + qx + px;
#pragma unroll
            for (int o = 0; o < 8; o++) {
                int oc = oc0 + o;
                int idx = ((b*128 + oc)*HW + gy)*HW + gx;
                float u = acc[py][px][o] + bias[oc];
                out[idx] = liaf_update(u, &mem[idx], &spk[idx]);
            }
        }
}

__global__ __launch_bounds__(256, 2) void conv1_kernel(
    const float* __restrict__ W, const float* __restrict__ bias)
{
    conv_body<64, 32>(g_act0, W, bias, g_act1, g_c1_mem, g_c1_spk);
}

__global__ __launch_bounds__(256, 2) void conv2_kernel(
    const float* __restrict__ W, const float* __restrict__ bias)
{
    conv_body<128, 16>(g_actp1, W, bias, g_actc2, g_c2_mem, g_c2_spk);
}

// ---------------- pool + LIAF ----------------
__global__ void pool1_kernel() {
    int i = blockIdx.x * blockDim.x + threadIdx.x;
    if (i >= BATCH*128*16*16) return;
    int x = i & 15, y = (i >> 4) & 15, bc = i >> 8;
    const float* base = g_act1 + (size_t)(bc*32 + 2*y)*32 + 2*x;
    float u = 0.25f * (base[0] + base[1] + base[32] + base[33]);
    g_actp1[i] = liaf_update(u, &g_p1_mem[i], &g_p1_spk[i]);
}

__global__ void pool2_kernel() {
    int i = blockIdx.x * blockDim.x + threadIdx.x;
    if (i >= BATCH*128*8*8) return;
    int x = i & 7, y = (i >> 3) & 7, bc = i >> 6;
    const float* base = g_actc2 + (size_t)(bc*16 + 2*y)*16 + 2*x;
    float u = 0.25f * (base[0] + base[1] + base[16] + base[17]);
    g_actp2[i] = liaf_update(u, &g_p2_mem[i], &g_p2_spk[i]);
}

// ---------------- FC1: 8192 -> 256 + LIAF ----------------
// grid (32, 36), block 256 (8 warps = 8 outputs/block)
__global__ void fc1_kernel(const float* __restrict__ Wf1, const float* __restrict__ bf1) {
    int b = blockIdx.y;
    int warp = threadIdx.x >> 5, lane = threadIdx.x & 31;
    int o = blockIdx.x * 8 + warp;
    const float4* xp = (const float4*)(g_actp2 + (size_t)b * 8192);
    const float4* wp = (const float4*)(Wf1 + (size_t)o * 8192);
    float s = 0.f;
#pragma unroll 8
    for (int i = lane; i < 2048; i += 32) {
        float4 x = xp[i], w = wp[i];
        s += x.x*w.x; s += x.y*w.y; s += x.z*w.z; s += x.w*w.w;
    }
#pragma unroll
    for (int off = 16; off; off >>= 1) s += __shfl_down_sync(0xffffffffu, s, off);
    if (lane == 0) {
        int idx = b*256 + o;
        g_acth1[idx] = liaf_update(s + bf1[o], &g_h1_mem[idx], &g_h1_spk[idx]);
    }
}

// ---------------- FC2: 256 -> 11 + LIAF + accumulate ----------------
// grid 36, block 384 (warps 0..10 active)
__global__ void fc2_kernel(const float* __restrict__ Wf2, const float* __restrict__ bf2) {
    int b = blockIdx.x;
    int warp = threadIdx.x >> 5, lane = threadIdx.x & 31;
    if (warp >= 11) return;
    float s = 0.f;
#pragma unroll
    for (int k = lane; k < 256; k += 32)
        s += g_acth1[b*256 + k] * Wf2[warp*256 + k];
#pragma unroll
    for (int off = 16; off; off >>= 1) s += __shfl_down_sync(0xffffffffu, s, off);
    if (lane == 0) {
        int idx = b*11 + warp;
        float o = liaf_update(s + bf2[warp], &g_h2_mem[idx], &g_h2_spk[idx]);
        g_acc[idx] += o;
    }
}

// ---------------- finalize ----------------
__global__ void finalize_kernel(float* __restrict__ out) {
    int i = threadIdx.x;
    if (i < BATCH*11) out[i] = g_acc[i] * (1.0f / (float)TWIN);
}

extern "C" void kernel_launch(void* const* d_in, const int* in_sizes, int n_in,
                              void* d_out, int out_size) {
    (void)in_sizes; (void)n_in; (void)out_size;
    const float* data = (const float*)d_in[0];
    // d_in[1] = win (== 60, fixed)
    const float* W0  = (const float*)d_in[2];
    const float* b0  = (const float*)d_in[3];
    const float* W1  = (const float*)d_in[4];
    const float* b1  = (const float*)d_in[5];
    const float* W2  = (const float*)d_in[6];
    const float* b2  = (const float*)d_in[7];
    const float* Wf1 = (const float*)d_in[8];
    const float* bf1 = (const float*)d_in[9];
    const float* Wf2 = (const float*)d_in[10];
    const float* bf2 = (const float*)d_in[11];

    zero_state_kernel<<<(BATCH*128*32*32 + 255)/256, 256>>>();

    for (int t = 0; t < TWIN; t++) {
        conv0_kernel<<<dim3(16, BATCH), 256>>>(data, W0, b0, t);
        conv1_kernel<<<dim3(16, BATCH), 256>>>(W1, b1);
        pool1_kernel<<<(BATCH*128*16*16 + 255)/256, 256>>>();
        conv2_kernel<<<dim3(4, BATCH), 256>>>(W2, b2);
        pool2_kernel<<<(BATCH*128*8*8 + 255)/256, 256>>>();
        fc1_kernel<<<dim3(32, BATCH), 256>>>(Wf1, bf1);
        fc2_kernel<<<BATCH, 384>>>(Wf2, bf2);
    }

    finalize_kernel<<<1, 512>>>((float*)d_out);
}